// round 14
// baseline (speedup 1.0000x reference)
#include <cuda_runtime.h>
#include <cuda_bf16.h>
#include <cstdint>

#define N_TOK 81920
#define C 256
#define SIGMA 0.0001f
#define LEAK 0.2f
#define NTC (N_TOK * C)

// ---- scratch (device globals: no allocs allowed) ----
__device__ float g_h[NTC];                  // final hidden (for decode)
__device__ float g_qkv3[3 * N_TOK * 768];   // q|k|v per axis (fp32)
__device__ __nv_bfloat16 g_hh[NTC];         // hidden state hi/lo split (bf16)
__device__ __nv_bfloat16 g_hl[NTC];
__device__ __nv_bfloat16 g_oh[3 * NTC];     // attn output hi/lo split, per axis
__device__ __nv_bfloat16 g_ol[3 * NTC];
#define W_TOTAL 1572864                     // Wq(393216) | Wkv(786432) | Wo(393216)
#define WKV_BASE 393216
#define WO_BASE 1179648
__device__ __nv_bfloat16 g_wh[W_TOTAL];
__device__ __nv_bfloat16 g_wl[W_TOTAL];

// ============================================================ helpers
__device__ __forceinline__ void split1(float a, uint16_t& h, uint16_t& l) {
    __nv_bfloat16 ha = __float2bfloat16(a);
    float ra = a - __bfloat162float(ha);
    __nv_bfloat16 la = __float2bfloat16(ra);
    h = __bfloat16_as_ushort(ha);
    l = __bfloat16_as_ushort(la);
}
__device__ __forceinline__ uint32_t s2u(const void* p) {
    uint32_t a;
    asm("{ .reg .u64 t; cvta.to.shared.u64 t, %1; cvt.u32.u64 %0, t; }" : "=r"(a) : "l"(p));
    return a;
}
__device__ __forceinline__ void mma_bf16(float* d, const uint32_t* a, const uint32_t* b) {
    asm volatile(
        "mma.sync.aligned.m16n8k16.row.col.f32.bf16.bf16.f32 "
        "{%0,%1,%2,%3}, {%4,%5,%6,%7}, {%8,%9}, {%0,%1,%2,%3};"
        : "+f"(d[0]), "+f"(d[1]), "+f"(d[2]), "+f"(d[3])
        : "r"(a[0]), "r"(a[1]), "r"(a[2]), "r"(a[3]), "r"(b[0]), "r"(b[1]));
}
__device__ __forceinline__ void ldm4(uint32_t* r, uint32_t addr) {
    asm volatile("ldmatrix.sync.aligned.m8n8.x4.shared.b16 {%0,%1,%2,%3}, [%4];"
                 : "=r"(r[0]), "=r"(r[1]), "=r"(r[2]), "=r"(r[3]) : "r"(addr));
}
__device__ __forceinline__ void ldm4t(uint32_t* r, uint32_t addr) {
    asm volatile("ldmatrix.sync.aligned.m8n8.x4.trans.shared.b16 {%0,%1,%2,%3}, [%4];"
                 : "=r"(r[0]), "=r"(r[1]), "=r"(r[2]), "=r"(r[3]) : "r"(addr));
}
__device__ __forceinline__ void cp16(uint32_t dst, const void* src) {
    uint64_t gp;
    asm("cvta.to.global.u64 %0, %1;" : "=l"(gp) : "l"(src));
    asm volatile("cp.async.cg.shared.global [%0], [%1], 16;" :: "r"(dst), "l"(gp));
}
#define SWZ(o) ((o) ^ (((o) >> 3) & 0x70))

// smem layout per stage (bf16, 128B swizzled rows)
#define SM_AH 0u          // 128 x 64 bf16 = 16384 B
#define SM_AL 16384u
#define SM_BH 32768u      // 64 x 64 bf16 = 8192 B
#define SM_BL 40960u
#define STAGE 49152u
#define SMEM_GEMM 98304   // 2 stages

// ============================================================ weight split (once)
__global__ void split_w_kernel(const float* __restrict__ Wq, const float* __restrict__ Wkv,
                               const float* __restrict__ Wo) {
    int idx = blockIdx.x * 256 + threadIdx.x;
    float v;
    if (idx < WKV_BASE)       v = Wq[idx];
    else if (idx < WO_BASE)   v = Wkv[idx - WKV_BASE];
    else                      v = Wo[idx - WO_BASE];
    uint16_t h, l;
    split1(v, h, l);
    g_wh[idx] = __ushort_as_bfloat16(h);
    g_wl[idx] = __ushort_as_bfloat16(l);
}

// ============================================================ encoder
__global__ void encode_kernel(const float* __restrict__ x, const float* __restrict__ noise,
                              const float* __restrict__ rnd, const float* __restrict__ Wenc,
                              const float* __restrict__ pos) {
    int t = blockIdx.x, c = threadIdx.x;
    float a = x[t] + SIGMA * noise[t];
    float r = rnd[t];
    float v = tanhf(a * Wenc[c] + r * Wenc[C + c]) + pos[(t % 160) * C + c];
    uint16_t h, l;
    split1(v, h, l);
    g_hh[t * C + c] = __ushort_as_bfloat16(h);
    g_hl[t * C + c] = __ushort_as_bfloat16(l);
}

// ============================================================ fragment-loop core
struct FragCtx {
    uint32_t smb;
    int a_row, a_cb, b_row, b_cb0;
};
__device__ __forceinline__ void frag_init(FragCtx& fc, uint32_t smb, int wid, int lane) {
    int wm = (wid >> 1) * 32, wn = (wid & 1) * 32;
    int lr = lane & 7, tsel = lane >> 3;
    fc.smb = smb;
    fc.a_row = wm + (tsel & 1) * 8 + lr;
    fc.a_cb = (tsel >> 1) * 16;
    fc.b_row = (tsel & 1) * 8 + lr;
    fc.b_cb0 = (wn + (tsel >> 1) * 8) * 2;
}
__device__ __forceinline__ void frag_chunk(const FragCtx& fc, int s, float d[2][4][4]) {
    uint32_t base = fc.smb + s * STAGE;
    #pragma unroll
    for (int ks = 0; ks < 4; ks++) {
        uint32_t ah[2][4], al[2][4], bh[2][4], bl[2][4];
        #pragma unroll
        for (int mi = 0; mi < 2; mi++) {
            uint32_t off = (uint32_t)((fc.a_row + mi * 16) * 128 + ks * 32 + fc.a_cb);
            ldm4(ah[mi], base + SM_AH + SWZ(off));
            ldm4(al[mi], base + SM_AL + SWZ(off));
        }
        #pragma unroll
        for (int p = 0; p < 2; p++) {
            uint32_t off = (uint32_t)((ks * 16 + fc.b_row) * 128 + fc.b_cb0 + p * 32);
            ldm4t(bh[p], base + SM_BH + SWZ(off));
            ldm4t(bl[p], base + SM_BL + SWZ(off));
        }
        #pragma unroll
        for (int mi = 0; mi < 2; mi++)
            #pragma unroll
            for (int ni = 0; ni < 4; ni++) {
                const uint32_t* bhf = &bh[ni >> 1][(ni & 1) * 2];
                const uint32_t* blf = &bl[ni >> 1][(ni & 1) * 2];
                mma_bf16(d[mi][ni], ah[mi], bhf);
                mma_bf16(d[mi][ni], al[mi], bhf);
                mma_bf16(d[mi][ni], ah[mi], blf);
            }
    }
}
// stage one 64-K chunk: A (128x64, hi/lo) and B (64x64, hi/lo)
__device__ __forceinline__ void stage_chunk(
    uint32_t smb, int s, int tid,
    const __nv_bfloat16* Agh, const __nv_bfloat16* Agl, int a_off,   // + r*256 per row
    int b_off, int ldb) {
    uint32_t base = smb + s * STAGE;
    #pragma unroll
    for (int i = 0; i < 8; i++) {
        int seg = tid + i * 256;
        int half = seg >> 10;
        int r = (seg & 1023) >> 3;
        int c8 = seg & 7;
        uint32_t off = (uint32_t)(r * 128 + c8 * 16);
        uint32_t dst = base + (half ? SM_AL : SM_AH) + SWZ(off);
        cp16(dst, (half ? Agl : Agh) + a_off + r * 256 + c8 * 8);
    }
    #pragma unroll
    for (int i = 0; i < 4; i++) {
        int seg = tid + i * 256;
        int half = seg >> 9;
        int r = (seg & 511) >> 3;
        int c8 = seg & 7;
        uint32_t off = (uint32_t)(r * 128 + c8 * 16);
        uint32_t dst = base + (half ? SM_BL : SM_BH) + SWZ(off);
        cp16(dst, (half ? g_wl : g_wh) + b_off + r * ldb + c8 * 8);
    }
    asm volatile("cp.async.commit_group;");
}

// ============================================================ qkv GEMM (all 3 axes, 36 n-chunks)
__global__ __launch_bounds__(256, 2) void gemm_qkv(int l) {
    extern __shared__ char sm[];
    uint32_t smb = s2u(sm);
    int tid = threadIdx.x, wid = tid >> 5, lane = tid & 31;
    int g = lane >> 2, t4 = lane & 3;
    int nc = blockIdx.x, m0 = blockIdx.y * 128;
    int axis = nc / 12, c12 = nc - axis * 12;
    int w = l * 3 + axis;
    int boff, ldb;
    if (c12 < 4) { boff = w * 65536 + c12 * 64; ldb = 256; }
    else         { boff = WKV_BASE + w * 131072 + (c12 - 4) * 64; ldb = 512; }

    FragCtx fc;
    frag_init(fc, smb, wid, lane);
    float d[2][4][4];
    #pragma unroll
    for (int mi = 0; mi < 2; mi++)
        #pragma unroll
        for (int ni = 0; ni < 4; ni++)
            #pragma unroll
            for (int r = 0; r < 4; r++) d[mi][ni][r] = 0.f;

    stage_chunk(smb, 0, tid, g_hh, g_hl, m0 * 256, boff, ldb);
    #pragma unroll
    for (int kc = 0; kc < 4; kc++) {
        asm volatile("cp.async.wait_group 0;" ::: "memory");
        __syncthreads();
        if (kc < 3)
            stage_chunk(smb, (kc + 1) & 1, tid, g_hh, g_hl,
                        m0 * 256 + (kc + 1) * 64, boff + (kc + 1) * 64 * ldb, ldb);
        frag_chunk(fc, kc & 1, d);
        __syncthreads();
    }

    int wm = (wid >> 1) * 32, wn = (wid & 1) * 32;
    float* dstb = g_qkv3 + axis * (N_TOK * 768) + c12 * 64;
    #pragma unroll
    for (int mi = 0; mi < 2; mi++)
        #pragma unroll
        for (int ni = 0; ni < 4; ni++)
            #pragma unroll
            for (int half = 0; half < 2; half++) {
                int row = m0 + wm + mi * 16 + g + half * 8;
                int col = wn + ni * 8 + 2 * t4;
                *(float2*)(dstb + row * 768 + col) =
                    make_float2(d[mi][ni][half * 2], d[mi][ni][half * 2 + 1]);
            }
}

// ============================================================ merged out-projection GEMM
// h_new = leaky( sum_a o_a @ Wo_a + sum_a bo_a ), K = 768 (12 chunks)
// write_h=0: write only bf16 splits (feeds next layer); write_h=1: write only fp32 g_h (feeds decode)
__global__ __launch_bounds__(256, 2) void gemm_out(int l, const float* __restrict__ bo, int write_h) {
    extern __shared__ char sm[];
    uint32_t smb = s2u(sm);
    int tid = threadIdx.x, wid = tid >> 5, lane = tid & 31;
    int g = lane >> 2, t4 = lane & 3;
    int nc = blockIdx.x, m0 = blockIdx.y * 128;

    FragCtx fc;
    frag_init(fc, smb, wid, lane);
    float d[2][4][4];
    #pragma unroll
    for (int mi = 0; mi < 2; mi++)
        #pragma unroll
        for (int ni = 0; ni < 4; ni++)
            #pragma unroll
            for (int r = 0; r < 4; r++) d[mi][ni][r] = 0.f;

    auto issue = [&](int kc, int s) {
        int axis = kc >> 2, c4 = kc & 3;
        stage_chunk(smb, s, tid,
                    g_oh + axis * NTC, g_ol + axis * NTC,
                    m0 * 256 + c4 * 64,
                    WO_BASE + (l * 3 + axis) * 65536 + c4 * 64 * 256 + nc * 64, 256);
    };

    issue(0, 0);
    #pragma unroll
    for (int kc = 0; kc < 12; kc++) {
        asm volatile("cp.async.wait_group 0;" ::: "memory");
        __syncthreads();
        if (kc < 11) issue(kc + 1, (kc + 1) & 1);
        frag_chunk(fc, kc & 1, d);
        __syncthreads();
    }

    const float* bl3 = bo + l * 3 * C;
    int wm = (wid >> 1) * 32, wn = (wid & 1) * 32;
    #pragma unroll
    for (int mi = 0; mi < 2; mi++)
        #pragma unroll
        for (int ni = 0; ni < 4; ni++)
            #pragma unroll
            for (int half = 0; half < 2; half++) {
                int row = m0 + wm + mi * 16 + g + half * 8;
                int col = nc * 64 + wn + ni * 8 + 2 * t4;
                float b0 = bl3[col] + bl3[C + col] + bl3[2 * C + col];
                float b1 = bl3[col + 1] + bl3[C + col + 1] + bl3[2 * C + col + 1];
                float s0 = d[mi][ni][half * 2] + b0;
                float s1 = d[mi][ni][half * 2 + 1] + b1;
                float o0 = s0 >= 0.f ? s0 : LEAK * s0;
                float o1 = s1 >= 0.f ? s1 : LEAK * s1;
                if (write_h) {
                    *(float2*)(g_h + row * 256 + col) = make_float2(o0, o1);
                } else {
                    uint16_t h0, l0, h1, l1;
                    split1(o0, h0, l0);
                    split1(o1, h1, l1);
                    *(uint32_t*)(g_hh + row * 256 + col) = (uint32_t)h0 | ((uint32_t)h1 << 16);
                    *(uint32_t*)(g_hl + row * 256 + col) = (uint32_t)l0 | ((uint32_t)l1 << 16);
                }
            }
}

// ============================================================ attention (separate launch per axis)
// Two-phase staging: q,k first; after logits, v REUSES the q buffer (q is dead).
// Cuts smem ~17KB/CTA -> 4 CTAs/SM.
template <int T, int G, int AXIS>
__global__ __launch_bounds__(256, 4) void attn_kernel(int axis) {
    constexpr int TT = T * G;
    constexpr int TTP = TT + 1;          // 17, 17, 21 -> coprime with 32
    extern __shared__ char smem_raw[];
    float* qsT = (float*)smem_raw;       // [256][TTP]  (phase 2: holds v)
    float* ksT = qsT + C * TTP;
    float* probs = ksT + C * TTP;        // [G][16][T][T]
    int* s_tok = (int*)(probs + G * 16 * T * T);

    int tid = threadIdx.x;
    int bx = blockIdx.x;
    const float* qkv = g_qkv3 + axis * (N_TOK * 768);

    if (tid < TT) {
        int gi = tid / T, t = tid % T;
        int g = bx * G + gi;
        int base, stride;
        if (AXIS == 1)      { base = (g / 20) * 160 + (g % 20); stride = 20; }
        else if (AXIS == 2) { int b = g / 40, r = g % 40;
                              base = b * 160 + (r / 5) * 20 + (r % 5); stride = 5; }
        else                { base = (g / 32) * 160 + (g % 32) * 5; stride = 1; }
        s_tok[tid] = base + t * stride;
    }
    __syncthreads();

    // phase 1: stage q,k transposed (coalesced LDG, conflict-free STS)
    #pragma unroll
    for (int r = 0; r < TT; r++) {
        int base = s_tok[r] * 768;
        qsT[tid * TTP + r] = qkv[base + tid];
        ksT[tid * TTP + r] = qkv[base + 256 + tid];
    }
    __syncthreads();

    // logits: q broadcast across ts, k unit-stride in ts
    for (int i = tid; i < G * 16 * T * T; i += 256) {
        int gi = i / (16 * T * T);
        int r = i % (16 * T * T);
        int head = r / (T * T);
        int rr = r % (T * T);
        int tq = rr / T, ts = rr % T;
        const float* qp = qsT + head * 16 * TTP + gi * T + tq;
        const float* kp = ksT + head * 16 * TTP + gi * T + ts;
        float s = 0.f;
        #pragma unroll
        for (int d = 0; d < 16; d++) s += qp[d * TTP] * kp[d * TTP];
        probs[i] = 0.25f * s;
    }
    __syncthreads();   // logits done: q buffer is dead, safe to overwrite with v

    // phase 2: stage v into the q buffer; softmax in parallel
    #pragma unroll
    for (int r = 0; r < TT; r++)
        qsT[tid * TTP + r] = qkv[s_tok[r] * 768 + 512 + tid];

    for (int i = tid; i < G * 16 * T; i += 256) {
        float* row = probs + i * T;
        float m = row[0];
        #pragma unroll
        for (int s = 1; s < T; s++) m = fmaxf(m, row[s]);
        float e[T];
        float sum = 0.f;
        #pragma unroll
        for (int s = 0; s < T; s++) { e[s] = expf(row[s] - m); sum += e[s]; }
        float inv = 1.f / sum;
        #pragma unroll
        for (int s = 0; s < T; s++) row[s] = e[s] * inv;
    }
    __syncthreads();

    // AV: per-thread channel row (stride-TTP across threads: conflict-free)
    int head = tid >> 4;
    const float* vrow = qsT + tid * TTP;
    __nv_bfloat16* oh = g_oh + axis * NTC;
    __nv_bfloat16* ol = g_ol + axis * NTC;
    #pragma unroll
    for (int tt = 0; tt < TT; tt++) {
        int gi = tt / T, t = tt % T;
        const float* pr = probs + ((gi * 16 + head) * T + t) * T;
        float o = 0.f;
        #pragma unroll
        for (int s = 0; s < T; s++) o += pr[s] * vrow[gi * T + s];
        uint16_t h, l;
        split1(o, h, l);
        oh[s_tok[tt] * C + tid] = __ushort_as_bfloat16(h);
        ol[s_tok[tt] * C + tid] = __ushort_as_bfloat16(l);
    }
}

// ============================================================ decoder
__global__ void decode_kernel(const float* __restrict__ Wd, const float* __restrict__ bd,
                              float* __restrict__ out) {
    int t = blockIdx.x * 8 + (threadIdx.x >> 5);
    int lane = threadIdx.x & 31;
    const float* hr = g_h + t * C;
    float s = 0.f;
    #pragma unroll
    for (int c = lane; c < C; c += 32) s += hr[c] * Wd[c];
    #pragma unroll
    for (int o = 16; o > 0; o >>= 1) s += __shfl_xor_sync(0xffffffffu, s, o);
    if (lane == 0) out[t] = 1.f / (1.f + expf(-(s + bd[0])));
}

// ============================================================ launch
static constexpr int attn_smem(int T, int G) {
    int TTP = T * G + 1;
    return 2 * C * TTP * 4 + G * 16 * T * T * 4 + T * G * 4;
}

extern "C" void kernel_launch(void* const* d_in, const int* in_sizes, int n_in,
                              void* d_out, int out_size) {
    const float* x     = (const float*)d_in[0];
    const float* noise = (const float*)d_in[1];
    const float* rnd   = (const float*)d_in[2];
    const float* Wenc  = (const float*)d_in[3];
    const float* pos   = (const float*)d_in[4];
    const float* Wq    = (const float*)d_in[5];
    const float* Wkv   = (const float*)d_in[6];
    const float* Wo    = (const float*)d_in[7];
    const float* bo    = (const float*)d_in[8];
    const float* Wd    = (const float*)d_in[9];
    const float* bd    = (const float*)d_in[10];
    float* out = (float*)d_out;

    constexpr int SA1 = attn_smem(8, 2);
    constexpr int SA2 = attn_smem(4, 4);
    constexpr int SA3 = attn_smem(5, 4);

    cudaFuncSetAttribute(gemm_qkv, cudaFuncAttributeMaxDynamicSharedMemorySize, SMEM_GEMM);
    cudaFuncSetAttribute(gemm_out, cudaFuncAttributeMaxDynamicSharedMemorySize, SMEM_GEMM);
    cudaFuncSetAttribute(attn_kernel<8, 2, 1>, cudaFuncAttributeMaxDynamicSharedMemorySize, SA1);
    cudaFuncSetAttribute(attn_kernel<4, 4, 2>, cudaFuncAttributeMaxDynamicSharedMemorySize, SA2);
    cudaFuncSetAttribute(attn_kernel<5, 4, 3>, cudaFuncAttributeMaxDynamicSharedMemorySize, SA3);

    split_w_kernel<<<W_TOTAL / 256, 256>>>(Wq, Wkv, Wo);
    encode_kernel<<<N_TOK, 256>>>(x, noise, rnd, Wenc, pos);

    for (int l = 0; l < 2; l++) {
        gemm_qkv<<<dim3(36, 640), 256, SMEM_GEMM>>>(l);
        attn_kernel<8, 2, 1><<<5120, 256, SA1>>>(0);
        attn_kernel<4, 4, 2><<<5120, 256, SA2>>>(1);
        attn_kernel<5, 4, 3><<<4096, 256, SA3>>>(2);
        gemm_out<<<dim3(4, 640), 256, SMEM_GEMM>>>(l, bo, l == 1 ? 1 : 0);
    }

    decode_kernel<<<10240, 256>>>(Wd, bd, out);
}

// round 15
// speedup vs baseline: 1.0013x; 1.0013x over previous
#include <cuda_runtime.h>
#include <cuda_bf16.h>
#include <cstdint>

#define N_TOK 81920
#define C 256
#define SIGMA 0.0001f
#define LEAK 0.2f
#define NTC (N_TOK * C)

// ---- scratch (device globals: no allocs allowed) ----
__device__ float g_h[NTC];                  // final hidden (for decode)
__device__ float g_qkv3[3 * N_TOK * 768];   // q|k|v per axis (fp32)
__device__ __nv_bfloat16 g_hh[NTC];         // hidden state hi/lo split (bf16)
__device__ __nv_bfloat16 g_hl[NTC];
__device__ __nv_bfloat16 g_oh[3 * NTC];     // attn output hi/lo split, per axis
__device__ __nv_bfloat16 g_ol[3 * NTC];
#define W_TOTAL 1572864                     // Wq(393216) | Wkv(786432) | Wo(393216)
#define WKV_BASE 393216
#define WO_BASE 1179648
__device__ __nv_bfloat16 g_wh[W_TOTAL];
__device__ __nv_bfloat16 g_wl[W_TOTAL];

// ============================================================ helpers
__device__ __forceinline__ void split1(float a, uint16_t& h, uint16_t& l) {
    __nv_bfloat16 ha = __float2bfloat16(a);
    float ra = a - __bfloat162float(ha);
    __nv_bfloat16 la = __float2bfloat16(ra);
    h = __bfloat16_as_ushort(ha);
    l = __bfloat16_as_ushort(la);
}
__device__ __forceinline__ uint32_t s2u(const void* p) {
    uint32_t a;
    asm("{ .reg .u64 t; cvta.to.shared.u64 t, %1; cvt.u32.u64 %0, t; }" : "=r"(a) : "l"(p));
    return a;
}
__device__ __forceinline__ void mma_bf16(float* d, const uint32_t* a, const uint32_t* b) {
    asm volatile(
        "mma.sync.aligned.m16n8k16.row.col.f32.bf16.bf16.f32 "
        "{%0,%1,%2,%3}, {%4,%5,%6,%7}, {%8,%9}, {%0,%1,%2,%3};"
        : "+f"(d[0]), "+f"(d[1]), "+f"(d[2]), "+f"(d[3])
        : "r"(a[0]), "r"(a[1]), "r"(a[2]), "r"(a[3]), "r"(b[0]), "r"(b[1]));
}
__device__ __forceinline__ void ldm4(uint32_t* r, uint32_t addr) {
    asm volatile("ldmatrix.sync.aligned.m8n8.x4.shared.b16 {%0,%1,%2,%3}, [%4];"
                 : "=r"(r[0]), "=r"(r[1]), "=r"(r[2]), "=r"(r[3]) : "r"(addr));
}
__device__ __forceinline__ void ldm4t(uint32_t* r, uint32_t addr) {
    asm volatile("ldmatrix.sync.aligned.m8n8.x4.trans.shared.b16 {%0,%1,%2,%3}, [%4];"
                 : "=r"(r[0]), "=r"(r[1]), "=r"(r[2]), "=r"(r[3]) : "r"(addr));
}
__device__ __forceinline__ void cp16(uint32_t dst, const void* src) {
    uint64_t gp;
    asm("cvta.to.global.u64 %0, %1;" : "=l"(gp) : "l"(src));
    asm volatile("cp.async.cg.shared.global [%0], [%1], 16;" :: "r"(dst), "l"(gp));
}
#define SWZ(o) ((o) ^ (((o) >> 3) & 0x70))

// smem layout per stage (bf16, 128B swizzled rows)
#define SM_AH 0u          // 128 x 64 bf16 = 16384 B
#define SM_AL 16384u
#define SM_BH 32768u      // 64 x 64 bf16 = 8192 B
#define SM_BL 40960u
#define STAGE 49152u
#define SMEM_GEMM 98304   // 2 stages

// ============================================================ weight split (once)
__global__ void split_w_kernel(const float* __restrict__ Wq, const float* __restrict__ Wkv,
                               const float* __restrict__ Wo) {
    int idx = blockIdx.x * 256 + threadIdx.x;
    float v;
    if (idx < WKV_BASE)       v = Wq[idx];
    else if (idx < WO_BASE)   v = Wkv[idx - WKV_BASE];
    else                      v = Wo[idx - WO_BASE];
    uint16_t h, l;
    split1(v, h, l);
    g_wh[idx] = __ushort_as_bfloat16(h);
    g_wl[idx] = __ushort_as_bfloat16(l);
}

// ============================================================ encoder
__global__ void encode_kernel(const float* __restrict__ x, const float* __restrict__ noise,
                              const float* __restrict__ rnd, const float* __restrict__ Wenc,
                              const float* __restrict__ pos) {
    int t = blockIdx.x, c = threadIdx.x;
    float a = x[t] + SIGMA * noise[t];
    float r = rnd[t];
    float v = tanhf(a * Wenc[c] + r * Wenc[C + c]) + pos[(t % 160) * C + c];
    uint16_t h, l;
    split1(v, h, l);
    g_hh[t * C + c] = __ushort_as_bfloat16(h);
    g_hl[t * C + c] = __ushort_as_bfloat16(l);
}

// ============================================================ fragment-loop core
struct FragCtx {
    uint32_t smb;
    int a_row, a_cb, b_row, b_cb0;
};
__device__ __forceinline__ void frag_init(FragCtx& fc, uint32_t smb, int wid, int lane) {
    int wm = (wid >> 1) * 32, wn = (wid & 1) * 32;
    int lr = lane & 7, tsel = lane >> 3;
    fc.smb = smb;
    fc.a_row = wm + (tsel & 1) * 8 + lr;
    fc.a_cb = (tsel >> 1) * 16;
    fc.b_row = (tsel & 1) * 8 + lr;
    fc.b_cb0 = (wn + (tsel >> 1) * 8) * 2;
}
__device__ __forceinline__ void frag_chunk(const FragCtx& fc, int s, float d[2][4][4]) {
    uint32_t base = fc.smb + s * STAGE;
    #pragma unroll
    for (int ks = 0; ks < 4; ks++) {
        uint32_t ah[2][4], al[2][4], bh[2][4], bl[2][4];
        #pragma unroll
        for (int mi = 0; mi < 2; mi++) {
            uint32_t off = (uint32_t)((fc.a_row + mi * 16) * 128 + ks * 32 + fc.a_cb);
            ldm4(ah[mi], base + SM_AH + SWZ(off));
            ldm4(al[mi], base + SM_AL + SWZ(off));
        }
        #pragma unroll
        for (int p = 0; p < 2; p++) {
            uint32_t off = (uint32_t)((ks * 16 + fc.b_row) * 128 + fc.b_cb0 + p * 32);
            ldm4t(bh[p], base + SM_BH + SWZ(off));
            ldm4t(bl[p], base + SM_BL + SWZ(off));
        }
        #pragma unroll
        for (int mi = 0; mi < 2; mi++)
            #pragma unroll
            for (int ni = 0; ni < 4; ni++) {
                const uint32_t* bhf = &bh[ni >> 1][(ni & 1) * 2];
                const uint32_t* blf = &bl[ni >> 1][(ni & 1) * 2];
                mma_bf16(d[mi][ni], ah[mi], bhf);
                mma_bf16(d[mi][ni], al[mi], bhf);
                mma_bf16(d[mi][ni], ah[mi], blf);
            }
    }
}
// stage one 64-K chunk: A (128x64, hi/lo) and B (64x64, hi/lo)
__device__ __forceinline__ void stage_chunk(
    uint32_t smb, int s, int tid,
    const __nv_bfloat16* Agh, const __nv_bfloat16* Agl, int a_off,   // + r*256 per row
    int b_off, int ldb) {
    uint32_t base = smb + s * STAGE;
    #pragma unroll
    for (int i = 0; i < 8; i++) {
        int seg = tid + i * 256;
        int half = seg >> 10;
        int r = (seg & 1023) >> 3;
        int c8 = seg & 7;
        uint32_t off = (uint32_t)(r * 128 + c8 * 16);
        uint32_t dst = base + (half ? SM_AL : SM_AH) + SWZ(off);
        cp16(dst, (half ? Agl : Agh) + a_off + r * 256 + c8 * 8);
    }
    #pragma unroll
    for (int i = 0; i < 4; i++) {
        int seg = tid + i * 256;
        int half = seg >> 9;
        int r = (seg & 511) >> 3;
        int c8 = seg & 7;
        uint32_t off = (uint32_t)(r * 128 + c8 * 16);
        uint32_t dst = base + (half ? SM_BL : SM_BH) + SWZ(off);
        cp16(dst, (half ? g_wl : g_wh) + b_off + r * ldb + c8 * 8);
    }
    asm volatile("cp.async.commit_group;");
}

// ============================================================ qkv GEMM (all 3 axes, 36 n-chunks)
__global__ __launch_bounds__(256, 2) void gemm_qkv(int l) {
    extern __shared__ char sm[];
    uint32_t smb = s2u(sm);
    int tid = threadIdx.x, wid = tid >> 5, lane = tid & 31;
    int g = lane >> 2, t4 = lane & 3;
    int nc = blockIdx.x, m0 = blockIdx.y * 128;
    int axis = nc / 12, c12 = nc - axis * 12;
    int w = l * 3 + axis;
    int boff, ldb;
    if (c12 < 4) { boff = w * 65536 + c12 * 64; ldb = 256; }
    else         { boff = WKV_BASE + w * 131072 + (c12 - 4) * 64; ldb = 512; }

    FragCtx fc;
    frag_init(fc, smb, wid, lane);
    float d[2][4][4];
    #pragma unroll
    for (int mi = 0; mi < 2; mi++)
        #pragma unroll
        for (int ni = 0; ni < 4; ni++)
            #pragma unroll
            for (int r = 0; r < 4; r++) d[mi][ni][r] = 0.f;

    stage_chunk(smb, 0, tid, g_hh, g_hl, m0 * 256, boff, ldb);
    #pragma unroll
    for (int kc = 0; kc < 4; kc++) {
        asm volatile("cp.async.wait_group 0;" ::: "memory");
        __syncthreads();
        if (kc < 3)
            stage_chunk(smb, (kc + 1) & 1, tid, g_hh, g_hl,
                        m0 * 256 + (kc + 1) * 64, boff + (kc + 1) * 64 * ldb, ldb);
        frag_chunk(fc, kc & 1, d);
        __syncthreads();
    }

    int wm = (wid >> 1) * 32, wn = (wid & 1) * 32;
    float* dstb = g_qkv3 + axis * (N_TOK * 768) + c12 * 64;
    #pragma unroll
    for (int mi = 0; mi < 2; mi++)
        #pragma unroll
        for (int ni = 0; ni < 4; ni++)
            #pragma unroll
            for (int half = 0; half < 2; half++) {
                int row = m0 + wm + mi * 16 + g + half * 8;
                int col = wn + ni * 8 + 2 * t4;
                *(float2*)(dstb + row * 768 + col) =
                    make_float2(d[mi][ni][half * 2], d[mi][ni][half * 2 + 1]);
            }
}

// ============================================================ merged out-projection GEMM
// h_new = leaky( sum_a o_a @ Wo_a + sum_a bo_a ), K = 768 (12 chunks)
// write_h=0: write only bf16 splits (feeds next layer); write_h=1: write only fp32 g_h (feeds decode)
__global__ __launch_bounds__(256, 2) void gemm_out(int l, const float* __restrict__ bo, int write_h) {
    extern __shared__ char sm[];
    uint32_t smb = s2u(sm);
    int tid = threadIdx.x, wid = tid >> 5, lane = tid & 31;
    int g = lane >> 2, t4 = lane & 3;
    int nc = blockIdx.x, m0 = blockIdx.y * 128;

    FragCtx fc;
    frag_init(fc, smb, wid, lane);
    float d[2][4][4];
    #pragma unroll
    for (int mi = 0; mi < 2; mi++)
        #pragma unroll
        for (int ni = 0; ni < 4; ni++)
            #pragma unroll
            for (int r = 0; r < 4; r++) d[mi][ni][r] = 0.f;

    auto issue = [&](int kc, int s) {
        int axis = kc >> 2, c4 = kc & 3;
        stage_chunk(smb, s, tid,
                    g_oh + axis * NTC, g_ol + axis * NTC,
                    m0 * 256 + c4 * 64,
                    WO_BASE + (l * 3 + axis) * 65536 + c4 * 64 * 256 + nc * 64, 256);
    };

    issue(0, 0);
    #pragma unroll
    for (int kc = 0; kc < 12; kc++) {
        asm volatile("cp.async.wait_group 0;" ::: "memory");
        __syncthreads();
        if (kc < 11) issue(kc + 1, (kc + 1) & 1);
        frag_chunk(fc, kc & 1, d);
        __syncthreads();
    }

    const float* bl3 = bo + l * 3 * C;
    int wm = (wid >> 1) * 32, wn = (wid & 1) * 32;
    #pragma unroll
    for (int mi = 0; mi < 2; mi++)
        #pragma unroll
        for (int ni = 0; ni < 4; ni++)
            #pragma unroll
            for (int half = 0; half < 2; half++) {
                int row = m0 + wm + mi * 16 + g + half * 8;
                int col = nc * 64 + wn + ni * 8 + 2 * t4;
                float b0 = bl3[col] + bl3[C + col] + bl3[2 * C + col];
                float b1 = bl3[col + 1] + bl3[C + col + 1] + bl3[2 * C + col + 1];
                float s0 = d[mi][ni][half * 2] + b0;
                float s1 = d[mi][ni][half * 2 + 1] + b1;
                float o0 = s0 >= 0.f ? s0 : LEAK * s0;
                float o1 = s1 >= 0.f ? s1 : LEAK * s1;
                if (write_h) {
                    *(float2*)(g_h + row * 256 + col) = make_float2(o0, o1);
                } else {
                    uint16_t h0, l0, h1, l1;
                    split1(o0, h0, l0);
                    split1(o1, h1, l1);
                    *(uint32_t*)(g_hh + row * 256 + col) = (uint32_t)h0 | ((uint32_t)h1 << 16);
                    *(uint32_t*)(g_hl + row * 256 + col) = (uint32_t)l0 | ((uint32_t)l1 << 16);
                }
            }
}

// ============================================================ attention (separate launch per axis)
// Two-phase staging: q,k first; after logits, v REUSES the q buffer (q is dead).
// Cuts smem ~17KB/CTA -> 4 CTAs/SM.
template <int T, int G, int AXIS>
__global__ __launch_bounds__(256, 4) void attn_kernel(int axis) {
    constexpr int TT = T * G;
    constexpr int TTP = TT + 1;          // 17, 17, 21 -> coprime with 32
    extern __shared__ char smem_raw[];
    float* qsT = (float*)smem_raw;       // [256][TTP]  (phase 2: holds v)
    float* ksT = qsT + C * TTP;
    float* probs = ksT + C * TTP;        // [G][16][T][T]
    int* s_tok = (int*)(probs + G * 16 * T * T);

    int tid = threadIdx.x;
    int bx = blockIdx.x;
    const float* qkv = g_qkv3 + axis * (N_TOK * 768);

    if (tid < TT) {
        int gi = tid / T, t = tid % T;
        int g = bx * G + gi;
        int base, stride;
        if (AXIS == 1)      { base = (g / 20) * 160 + (g % 20); stride = 20; }
        else if (AXIS == 2) { int b = g / 40, r = g % 40;
                              base = b * 160 + (r / 5) * 20 + (r % 5); stride = 5; }
        else                { base = (g / 32) * 160 + (g % 32) * 5; stride = 1; }
        s_tok[tid] = base + t * stride;
    }
    __syncthreads();

    // phase 1: stage q,k transposed (coalesced LDG, conflict-free STS)
    #pragma unroll
    for (int r = 0; r < TT; r++) {
        int base = s_tok[r] * 768;
        qsT[tid * TTP + r] = qkv[base + tid];
        ksT[tid * TTP + r] = qkv[base + 256 + tid];
    }
    __syncthreads();

    // logits: q broadcast across ts, k unit-stride in ts
    for (int i = tid; i < G * 16 * T * T; i += 256) {
        int gi = i / (16 * T * T);
        int r = i % (16 * T * T);
        int head = r / (T * T);
        int rr = r % (T * T);
        int tq = rr / T, ts = rr % T;
        const float* qp = qsT + head * 16 * TTP + gi * T + tq;
        const float* kp = ksT + head * 16 * TTP + gi * T + ts;
        float s = 0.f;
        #pragma unroll
        for (int d = 0; d < 16; d++) s += qp[d * TTP] * kp[d * TTP];
        probs[i] = 0.25f * s;
    }
    __syncthreads();   // logits done: q buffer is dead, safe to overwrite with v

    // phase 2: stage v into the q buffer; softmax in parallel
    #pragma unroll
    for (int r = 0; r < TT; r++)
        qsT[tid * TTP + r] = qkv[s_tok[r] * 768 + 512 + tid];

    for (int i = tid; i < G * 16 * T; i += 256) {
        float* row = probs + i * T;
        float m = row[0];
        #pragma unroll
        for (int s = 1; s < T; s++) m = fmaxf(m, row[s]);
        float e[T];
        float sum = 0.f;
        #pragma unroll
        for (int s = 0; s < T; s++) { e[s] = expf(row[s] - m); sum += e[s]; }
        float inv = 1.f / sum;
        #pragma unroll
        for (int s = 0; s < T; s++) row[s] = e[s] * inv;
    }
    __syncthreads();

    // AV: per-thread channel row (stride-TTP across threads: conflict-free)
    int head = tid >> 4;
    const float* vrow = qsT + tid * TTP;
    __nv_bfloat16* oh = g_oh + axis * NTC;
    __nv_bfloat16* ol = g_ol + axis * NTC;
    #pragma unroll
    for (int tt = 0; tt < TT; tt++) {
        int gi = tt / T, t = tt % T;
        const float* pr = probs + ((gi * 16 + head) * T + t) * T;
        float o = 0.f;
        #pragma unroll
        for (int s = 0; s < T; s++) o += pr[s] * vrow[gi * T + s];
        uint16_t h, l;
        split1(o, h, l);
        oh[s_tok[tt] * C + tid] = __ushort_as_bfloat16(h);
        ol[s_tok[tt] * C + tid] = __ushort_as_bfloat16(l);
    }
}

// ============================================================ decoder
__global__ void decode_kernel(const float* __restrict__ Wd, const float* __restrict__ bd,
                              float* __restrict__ out) {
    int t = blockIdx.x * 8 + (threadIdx.x >> 5);
    int lane = threadIdx.x & 31;
    const float* hr = g_h + t * C;
    float s = 0.f;
    #pragma unroll
    for (int c = lane; c < C; c += 32) s += hr[c] * Wd[c];
    #pragma unroll
    for (int o = 16; o > 0; o >>= 1) s += __shfl_xor_sync(0xffffffffu, s, o);
    if (lane == 0) out[t] = 1.f / (1.f + expf(-(s + bd[0])));
}

// ============================================================ launch
static constexpr int attn_smem(int T, int G) {
    int TTP = T * G + 1;
    return 2 * C * TTP * 4 + G * 16 * T * T * 4 + T * G * 4;
}

extern "C" void kernel_launch(void* const* d_in, const int* in_sizes, int n_in,
                              void* d_out, int out_size) {
    const float* x     = (const float*)d_in[0];
    const float* noise = (const float*)d_in[1];
    const float* rnd   = (const float*)d_in[2];
    const float* Wenc  = (const float*)d_in[3];
    const float* pos   = (const float*)d_in[4];
    const float* Wq    = (const float*)d_in[5];
    const float* Wkv   = (const float*)d_in[6];
    const float* Wo    = (const float*)d_in[7];
    const float* bo    = (const float*)d_in[8];
    const float* Wd    = (const float*)d_in[9];
    const float* bd    = (const float*)d_in[10];
    float* out = (float*)d_out;

    constexpr int SA1 = attn_smem(8, 2);
    constexpr int SA2 = attn_smem(4, 4);
    constexpr int SA3 = attn_smem(5, 4);

    cudaFuncSetAttribute(gemm_qkv, cudaFuncAttributeMaxDynamicSharedMemorySize, SMEM_GEMM);
    cudaFuncSetAttribute(gemm_out, cudaFuncAttributeMaxDynamicSharedMemorySize, SMEM_GEMM);
    cudaFuncSetAttribute(attn_kernel<8, 2, 1>, cudaFuncAttributeMaxDynamicSharedMemorySize, SA1);
    cudaFuncSetAttribute(attn_kernel<4, 4, 2>, cudaFuncAttributeMaxDynamicSharedMemorySize, SA2);
    cudaFuncSetAttribute(attn_kernel<5, 4, 3>, cudaFuncAttributeMaxDynamicSharedMemorySize, SA3);

    split_w_kernel<<<W_TOTAL / 256, 256>>>(Wq, Wkv, Wo);
    encode_kernel<<<N_TOK, 256>>>(x, noise, rnd, Wenc, pos);

    for (int l = 0; l < 2; l++) {
        gemm_qkv<<<dim3(36, 640), 256, SMEM_GEMM>>>(l);
        attn_kernel<8, 2, 1><<<5120, 256, SA1>>>(0);
        attn_kernel<4, 4, 2><<<5120, 256, SA2>>>(1);
        attn_kernel<5, 4, 3><<<4096, 256, SA3>>>(2);
        gemm_out<<<dim3(4, 640), 256, SMEM_GEMM>>>(l, bo, l == 1 ? 1 : 0);
    }

    decode_kernel<<<10240, 256>>>(Wd, bd, out);
}